// round 8
// baseline (speedup 1.0000x reference)
#include <cuda_runtime.h>
#include <cuda_bf16.h>

#define BS 2
#define NQ 8192
#define NV 6890
#define NF 13776
#define EPSF 1e-7f
#define R2F 0.01f        // f32(0.1*0.1) — matches JAX constant folding
#define NEG_R (-0.1f)
#define THRESHF 0.001f

#define GRIDC 10
#define NSUB (GRIDC * GRIDC * GRIDC)
#define CAP3 40
#define IMAXI 0x7fffffff
#define QBLOCKS (BS * NQ / 16)   // 2 queries/warp, 8 warps/block -> 1024 blocks

// Zero-initialized at module load; the last query block re-zeros everything
// at the end of each replay so the captured graph is self-consistent.
__device__ float4 g_vn[BS * NV];              // (nx,ny,nz,count)
__device__ int    g_cnt3[BS * NSUB];
__device__ float4 g_bins3[BS * NSUB * CAP3];  // (x,y,z,idx-as-float)
__device__ float  g_loss[2];                  // sum, count
__device__ unsigned int g_done;

// ---------------------------------------------------------------------------
// K1: fused 3D vertex binning + face-normal scatter (red.v4: 3 atomics/face)
// ---------------------------------------------------------------------------
__global__ void build_kernel(const float* __restrict__ h_state,
                             const int* __restrict__ h_faces) {
    int t = blockIdx.x * blockDim.x + threadIdx.x;

    if (t < BS * NV) {
        int b = t / NV, v = t - b * NV;
        const float* xs = h_state + b * 6 * NV;
        float x = __ldg(xs + v), y = __ldg(xs + NV + v), z = __ldg(xs + 2 * NV + v);
        int ix = min(max((int)(x * 10.0f), 0), GRIDC - 1);
        int iy = min(max((int)(y * 10.0f), 0), GRIDC - 1);
        int iz = min(max((int)(z * 10.0f), 0), GRIDC - 1);
        int sc = ((b * GRIDC + iy) * GRIDC + ix) * GRIDC + iz;
        int slot = atomicAdd(&g_cnt3[sc], 1);
        if (slot < CAP3)
            g_bins3[(size_t)sc * CAP3 + slot] = make_float4(x, y, z, __int_as_float(v));
    }

    if (t < BS * NF) {
        int b = t / NF, f = t - b * NF;
        const int* F = h_faces + b * 3 * NF;
        int i0 = __ldg(F + f), i1 = __ldg(F + NF + f), i2 = __ldg(F + 2 * NF + f);

        const float* xs = h_state + b * 6 * NV;
        const float* ys = xs + NV;
        const float* zs = xs + 2 * NV;

        float x0 = __ldg(xs + i0), y0 = __ldg(ys + i0), z0 = __ldg(zs + i0);
        float e1x = __ldg(xs + i1) - x0, e1y = __ldg(ys + i1) - y0, e1z = __ldg(zs + i1) - z0;
        float e2x = __ldg(xs + i2) - x0, e2y = __ldg(ys + i2) - y0, e2z = __ldg(zs + i2) - z0;

        float nx = e1y * e2z - e1z * e2y;
        float ny = e1z * e2x - e1x * e2z;
        float nz = e1x * e2y - e1y * e2x;
        float nrm = sqrtf(nx * nx + ny * ny + nz * nz) + EPSF;
        nx /= nrm; ny /= nrm; nz /= nrm;

        int base = b * NV;
        float one = 1.0f;
        asm volatile("red.global.add.v4.f32 [%0], {%1, %2, %3, %4};"
                     :: "l"(&g_vn[base + i0]), "f"(nx), "f"(ny), "f"(nz), "f"(one) : "memory");
        asm volatile("red.global.add.v4.f32 [%0], {%1, %2, %3, %4};"
                     :: "l"(&g_vn[base + i1]), "f"(nx), "f"(ny), "f"(nz), "f"(one) : "memory");
        asm volatile("red.global.add.v4.f32 [%0], {%1, %2, %3, %4};"
                     :: "l"(&g_vn[base + i2]), "f"(nx), "f"(ny), "f"(nz), "f"(one) : "memory");
    }
}

// ---------------------------------------------------------------------------
// K2: fused query + finalize. 16 lanes per query (2 queries/warp); the 16
// lanes split into two octets that scan two different columns concurrently
// (stride-8 within an octet). Min-4 merge over all 16 lanes unions the
// octets' finds. Loss tail on hlanes 0-3; last block finalizes + re-zeros.
// ---------------------------------------------------------------------------
__global__ void __launch_bounds__(256)
query_kernel(const float* __restrict__ pred,
             const float* __restrict__ h_state,
             float* __restrict__ out) {
    __shared__ float s_sum[16];
    __shared__ float s_cnt[16];
    __shared__ bool  s_last;

    int gwid  = (blockIdx.x * blockDim.x + threadIdx.x) >> 5;
    int lane  = threadIdx.x & 31;
    int hlane = lane & 15;             // lane within 16-lane query group
    int half  = lane >> 4;             // query slot within warp
    int octet = hlane >> 3;            // column-pair slot (0 or 1)
    int olane = hlane & 7;             // lane within octet
    int wib   = threadIdx.x >> 5;

    int gq = gwid * 2 + half;          // global query id (0..16383)
    int b  = gq >> 13;                 // batch (NQ = 8192)

    const float* P = pred + (size_t)gq * 3;
    float px = __ldg(P), py = __ldg(P + 1), pz = __ldg(P + 2);

    int ix = min(max((int)(px * 10.0f), 0), GRIDC - 1);
    int iy = min(max((int)(py * 10.0f), 0), GRIDC - 1);
    int iz = min(max((int)(pz * 10.0f), 0), GRIDC - 1);
    int cx0 = max(ix - 1, 0), cx1 = min(ix + 1, GRIDC - 1);
    int cy0 = max(iy - 1, 0), cy1 = min(iy + 1, GRIDC - 1);
    int cz0 = max(iz - 1, 0), cz1 = min(iz + 1, GRIDC - 1);
    int nzm1 = cz1 - cz0;
    int ncx = cx1 - cx0 + 1;
    int ncols = ncx * (cy1 - cy0 + 1); // 4, 6, or 9 columns

    int b0 = IMAXI, b1 = IMAXI, b2 = IMAXI, b3 = IMAXI;

    for (int p = 0; p < ncols; p += 2) {
        int ci = p + octet;
        int tot = 0, c0 = 0, c01 = 0;
        const float4* B0 = g_bins3;
        if (ci < ncols) {
            int cyq = ci / ncx;                    // ncx in {2,3}
            int cy = cy0 + cyq;
            int cx = cx0 + (ci - cyq * ncx);
            int sc = ((b * GRIDC + cy) * GRIDC + cx) * GRIDC + cz0;
            int n0 = min(__ldg(&g_cnt3[sc]), CAP3);
            int n1 = (nzm1 >= 1) ? min(__ldg(&g_cnt3[sc + 1]), CAP3) : 0;
            int n2 = (nzm1 >= 2) ? min(__ldg(&g_cnt3[sc + 2]), CAP3) : 0;
            c0 = n0; c01 = n0 + n1; tot = c01 + n2;
            B0 = g_bins3 + (size_t)sc * CAP3;
        }
        for (int s = olane; s < tot; s += 8) {
            const float4* B; int off;
            if (s < c0)        { B = B0;            off = s; }
            else if (s < c01)  { B = B0 + CAP3;     off = s - c0; }
            else               { B = B0 + 2 * CAP3; off = s - c01; }
            float4 v = __ldg(B + off);
            float dx = px - v.x, dy = py - v.y, dz = pz - v.z;
            if (dx * dx + dy * dy + dz * dz < R2F) {
                int id = __float_as_int(v.w);
                if (id < b3) {
                    b3 = id;
                    if (b3 < b2) { int t = b2; b2 = b3; b3 = t; }
                    if (b2 < b1) { int t = b1; b1 = b2; b2 = t; }
                    if (b1 < b0) { int t = b0; b0 = b1; b1 = t; }
                }
            }
        }
    }

    // Per-half merge: 4 successive minima via REDUX; hlane k keeps k-th.
    unsigned hm = half ? 0xFFFF0000u : 0x0000FFFFu;
    int mine = IMAXI, first = 0, cnt = 0;
    #pragma unroll
    for (int k = 0; k < 4; k++) {
        int m = (int)__reduce_min_sync(hm, (unsigned)b0);
        if (hlane == k) mine = m;
        if (k == 0 && m != IMAXI) first = m;
        if (m != IMAXI) cnt++;
        if (m != IMAXI && b0 == m) { b0 = b1; b1 = b2; b2 = b3; b3 = IMAXI; }
    }

    // Loss tail: hlanes 0-3 handle one neighbor each.
    float contrib = 0.0f, nmv = 0.0f;
    if (hlane < 4) {
        int i = (hlane < cnt) ? mine : first;   // idx=0 when no hits (argmax)
        const float* xs = h_state + b * 6 * NV;
        float vx = __ldg(xs + i);
        float vy = __ldg(xs + NV + i);
        float vz = __ldg(xs + 2 * NV + i);
        float4 vn = __ldg(&g_vn[b * NV + i]);
        float denom = vn.w + EPSF;
        float gx = vn.x / denom, gy = vn.y / denom, gz = vn.z / denom;
        float nr = sqrtf(gx * gx + gy * gy + gz * gz) + EPSF;
        gx /= nr; gy /= nr; gz /= nr;
        float dot = (px - vx) * gx + (py - vy) * gy + (pz - vz) * gz;
        float valid = (dot >= NEG_R) ? (dot - THRESHF) : 0.0f;
        if (valid < 0.0f) { contrib = valid; nmv = 1.0f; }
    }
    contrib += __shfl_xor_sync(0xffffffffu, contrib, 1);
    contrib += __shfl_xor_sync(0xffffffffu, contrib, 2);
    nmv     += __shfl_xor_sync(0xffffffffu, nmv, 1);
    nmv     += __shfl_xor_sync(0xffffffffu, nmv, 2);

    if (hlane == 0) {
        float pp = contrib / (nmv + EPSF);
        float pp2 = pp * pp;
        s_sum[wib * 2 + half] = pp2;
        s_cnt[wib * 2 + half] = (pp2 > 0.0f) ? 1.0f : 0.0f;
    }
    __syncthreads();

    if (threadIdx.x == 0) {
        float bs_ = 0.0f, bc_ = 0.0f;
        #pragma unroll
        for (int i = 0; i < 16; i++) { bs_ += s_sum[i]; bc_ += s_cnt[i]; }
        atomicAdd(&g_loss[0], bs_);
        atomicAdd(&g_loss[1], bc_);
        __threadfence();
        unsigned int n = atomicAdd(&g_done, 1u);
        s_last = (n == (unsigned int)(gridDim.x - 1));
    }
    __syncthreads();

    // Last block: finalize + re-zero scratch for the next graph replay.
    if (s_last) {
        int t = threadIdx.x;
        if (t == 0) {
            float ls = atomicAdd(&g_loss[0], 0.0f);
            float lc = atomicAdd(&g_loss[1], 0.0f);
            out[0] = ls / (lc + EPSF);     // LOSS_WEIGHT = 1
            g_loss[0] = 0.0f;
            g_loss[1] = 0.0f;
            g_done = 0u;
        }
        float4 z4 = make_float4(0.0f, 0.0f, 0.0f, 0.0f);
        for (int i = t; i < BS * NV; i += 256) g_vn[i] = z4;
        for (int i = t; i < BS * NSUB; i += 256) g_cnt3[i] = 0;
    }
}

// ---------------------------------------------------------------------------
extern "C" void kernel_launch(void* const* d_in, const int* in_sizes, int n_in,
                              void* d_out, int out_size) {
    const float* pred    = (const float*)d_in[0];   // (2, 8192, 3)
    const float* h_state = (const float*)d_in[2];   // (2, 6, 6890)
    const int*   h_faces = (const int*)d_in[3];     // (2, 3, 13776)
    float* out = (float*)d_out;

    int bn = BS * NF;   // covers BS*NV too (NF > NV)
    build_kernel<<<(bn + 127) / 128, 128>>>(h_state, h_faces);

    query_kernel<<<QBLOCKS, 256>>>(pred, h_state, out);
}

// round 9
// speedup vs baseline: 1.1525x; 1.1525x over previous
#include <cuda_runtime.h>
#include <cuda_bf16.h>

#define BS 2
#define NQ 8192
#define NV 6890
#define NF 13776
#define EPSF 1e-7f
#define R2F 0.01f        // f32(0.1*0.1) — matches JAX constant folding
#define NEG_R (-0.1f)
#define THRESHF 0.001f

#define GRIDC 10
#define NSUB (GRIDC * GRIDC * GRIDC)
#define CAP3 40
#define IMAXI 0x7fffffff
#define QBLOCKS (BS * NQ / 16)   // 2 queries/warp, 8 warps/block -> 1024 blocks

// Zero-initialized at module load; the last query block re-zeros everything
// at the end of each replay so the captured graph is self-consistent.
__device__ float4 g_vn[BS * NV];              // (nx,ny,nz,count)
__device__ int    g_cnt3[BS * NSUB];
__device__ float4 g_bins3[BS * NSUB * CAP3];  // (x,y,z,idx-as-float)
__device__ float  g_loss[2];                  // sum, count
__device__ unsigned int g_done;

// ---------------------------------------------------------------------------
// K1: fused 3D vertex binning + face-normal scatter (red.v4: 3 atomics/face)
// ---------------------------------------------------------------------------
__global__ void build_kernel(const float* __restrict__ h_state,
                             const int* __restrict__ h_faces) {
    int t = blockIdx.x * blockDim.x + threadIdx.x;

    if (t < BS * NV) {
        int b = t / NV, v = t - b * NV;
        const float* xs = h_state + b * 6 * NV;
        float x = __ldg(xs + v), y = __ldg(xs + NV + v), z = __ldg(xs + 2 * NV + v);
        int ix = min(max((int)(x * 10.0f), 0), GRIDC - 1);
        int iy = min(max((int)(y * 10.0f), 0), GRIDC - 1);
        int iz = min(max((int)(z * 10.0f), 0), GRIDC - 1);
        int sc = ((b * GRIDC + iy) * GRIDC + ix) * GRIDC + iz;
        int slot = atomicAdd(&g_cnt3[sc], 1);
        if (slot < CAP3)
            g_bins3[(size_t)sc * CAP3 + slot] = make_float4(x, y, z, __int_as_float(v));
    }

    if (t < BS * NF) {
        int b = t / NF, f = t - b * NF;
        const int* F = h_faces + b * 3 * NF;
        int i0 = __ldg(F + f), i1 = __ldg(F + NF + f), i2 = __ldg(F + 2 * NF + f);

        const float* xs = h_state + b * 6 * NV;
        const float* ys = xs + NV;
        const float* zs = xs + 2 * NV;

        float x0 = __ldg(xs + i0), y0 = __ldg(ys + i0), z0 = __ldg(zs + i0);
        float e1x = __ldg(xs + i1) - x0, e1y = __ldg(ys + i1) - y0, e1z = __ldg(zs + i1) - z0;
        float e2x = __ldg(xs + i2) - x0, e2y = __ldg(ys + i2) - y0, e2z = __ldg(zs + i2) - z0;

        float nx = e1y * e2z - e1z * e2y;
        float ny = e1z * e2x - e1x * e2z;
        float nz = e1x * e2y - e1y * e2x;
        float nrm = sqrtf(nx * nx + ny * ny + nz * nz) + EPSF;
        nx /= nrm; ny /= nrm; nz /= nrm;

        int base = b * NV;
        float one = 1.0f;
        asm volatile("red.global.add.v4.f32 [%0], {%1, %2, %3, %4};"
                     :: "l"(&g_vn[base + i0]), "f"(nx), "f"(ny), "f"(nz), "f"(one) : "memory");
        asm volatile("red.global.add.v4.f32 [%0], {%1, %2, %3, %4};"
                     :: "l"(&g_vn[base + i1]), "f"(nx), "f"(ny), "f"(nz), "f"(one) : "memory");
        asm volatile("red.global.add.v4.f32 [%0], {%1, %2, %3, %4};"
                     :: "l"(&g_vn[base + i2]), "f"(nx), "f"(ny), "f"(nz), "f"(one) : "memory");
    }
}

// ---------------------------------------------------------------------------
// K2: fused query + finalize. 16 lanes per query (2 queries/warp); two
// octets scan alternating columns of the FIXED 3x3 neighborhood (stride-8
// within an octet; constant-divisor decode; OOB columns skipped via tot=0).
// 16-lane REDUX merge unions the octets. Loss tail on hlanes 0-3; last
// block finalizes + re-zeros.
// ---------------------------------------------------------------------------
__global__ void __launch_bounds__(256)
query_kernel(const float* __restrict__ pred,
             const float* __restrict__ h_state,
             float* __restrict__ out) {
    __shared__ float s_sum[16];
    __shared__ float s_cnt[16];
    __shared__ bool  s_last;

    int gwid  = (blockIdx.x * blockDim.x + threadIdx.x) >> 5;
    int lane  = threadIdx.x & 31;
    int hlane = lane & 15;             // lane within 16-lane query group
    int half  = lane >> 4;             // query slot within warp
    int octet = hlane >> 3;            // column-stream slot (0 or 1)
    int olane = hlane & 7;             // lane within octet
    int wib   = threadIdx.x >> 5;

    int gq = gwid * 2 + half;          // global query id (0..16383)
    int b  = gq >> 13;                 // batch (NQ = 8192)

    const float* P = pred + (size_t)gq * 3;
    float px = __ldg(P), py = __ldg(P + 1), pz = __ldg(P + 2);

    int ix = min(max((int)(px * 10.0f), 0), GRIDC - 1);
    int iy = min(max((int)(py * 10.0f), 0), GRIDC - 1);
    int iz = min(max((int)(pz * 10.0f), 0), GRIDC - 1);
    int cz0 = max(iz - 1, 0), cz1 = min(iz + 1, GRIDC - 1);
    int nzm1 = cz1 - cz0;

    int b0 = IMAXI, b1 = IMAXI, b2 = IMAXI, b3 = IMAXI;

    // Fixed 3x3 neighborhood: ci enumerates (dy,dx); octets take odd/even ci.
    for (int ci = octet; ci < 9; ci += 2) {
        int dy = ci / 3;               // constant divisor -> mul+shift
        int dx = ci - dy * 3;
        int cy = iy - 1 + dy;
        int cx = ix - 1 + dx;
        bool ok = (cx >= 0) & (cx < GRIDC) & (cy >= 0) & (cy < GRIDC);

        int tot = 0, c0 = 0, c01 = 0;
        const float4* B0 = g_bins3;
        if (ok) {
            int sc = ((b * GRIDC + cy) * GRIDC + cx) * GRIDC + cz0;
            c0 = min(__ldg(&g_cnt3[sc]), CAP3);
            int n1 = (nzm1 >= 1) ? min(__ldg(&g_cnt3[sc + 1]), CAP3) : 0;
            int n2 = (nzm1 >= 2) ? min(__ldg(&g_cnt3[sc + 2]), CAP3) : 0;
            c01 = c0 + n1;
            tot = c01 + n2;
            B0 = g_bins3 + (size_t)sc * CAP3;
        }
        for (int s = olane; s < tot; s += 8) {
            const float4* B; int off;
            if (s < c0)        { B = B0;            off = s; }
            else if (s < c01)  { B = B0 + CAP3;     off = s - c0; }
            else               { B = B0 + 2 * CAP3; off = s - c01; }
            float4 v = __ldg(B + off);
            float ddx = px - v.x, ddy = py - v.y, ddz = pz - v.z;
            if (ddx * ddx + ddy * ddy + ddz * ddz < R2F) {
                int id = __float_as_int(v.w);
                if (id < b3) {
                    b3 = id;
                    if (b3 < b2) { int t = b2; b2 = b3; b3 = t; }
                    if (b2 < b1) { int t = b1; b1 = b2; b2 = t; }
                    if (b1 < b0) { int t = b0; b0 = b1; b1 = t; }
                }
            }
        }
    }

    // Per-half merge: 4 successive minima via REDUX; hlane k keeps k-th.
    unsigned hm = half ? 0xFFFF0000u : 0x0000FFFFu;
    int mine = IMAXI, first = 0, cnt = 0;
    #pragma unroll
    for (int k = 0; k < 4; k++) {
        int m = (int)__reduce_min_sync(hm, (unsigned)b0);
        if (hlane == k) mine = m;
        if (k == 0 && m != IMAXI) first = m;
        if (m != IMAXI) cnt++;
        if (m != IMAXI && b0 == m) { b0 = b1; b1 = b2; b2 = b3; b3 = IMAXI; }
    }

    // Loss tail: hlanes 0-3 handle one neighbor each.
    float contrib = 0.0f, nmv = 0.0f;
    if (hlane < 4) {
        int i = (hlane < cnt) ? mine : first;   // idx=0 when no hits (argmax)
        const float* xs = h_state + b * 6 * NV;
        float vx = __ldg(xs + i);
        float vy = __ldg(xs + NV + i);
        float vz = __ldg(xs + 2 * NV + i);
        float4 vn = __ldg(&g_vn[b * NV + i]);
        float denom = vn.w + EPSF;
        float gx = vn.x / denom, gy = vn.y / denom, gz = vn.z / denom;
        float nr = sqrtf(gx * gx + gy * gy + gz * gz) + EPSF;
        gx /= nr; gy /= nr; gz /= nr;
        float dot = (px - vx) * gx + (py - vy) * gy + (pz - vz) * gz;
        float valid = (dot >= NEG_R) ? (dot - THRESHF) : 0.0f;
        if (valid < 0.0f) { contrib = valid; nmv = 1.0f; }
    }
    contrib += __shfl_xor_sync(0xffffffffu, contrib, 1);
    contrib += __shfl_xor_sync(0xffffffffu, contrib, 2);
    nmv     += __shfl_xor_sync(0xffffffffu, nmv, 1);
    nmv     += __shfl_xor_sync(0xffffffffu, nmv, 2);

    if (hlane == 0) {
        float pp = contrib / (nmv + EPSF);
        float pp2 = pp * pp;
        s_sum[wib * 2 + half] = pp2;
        s_cnt[wib * 2 + half] = (pp2 > 0.0f) ? 1.0f : 0.0f;
    }
    __syncthreads();

    if (threadIdx.x == 0) {
        float bs_ = 0.0f, bc_ = 0.0f;
        #pragma unroll
        for (int i = 0; i < 16; i++) { bs_ += s_sum[i]; bc_ += s_cnt[i]; }
        atomicAdd(&g_loss[0], bs_);
        atomicAdd(&g_loss[1], bc_);
        __threadfence();
        unsigned int n = atomicAdd(&g_done, 1u);
        s_last = (n == (unsigned int)(gridDim.x - 1));
    }
    __syncthreads();

    // Last block: finalize + re-zero scratch for the next graph replay.
    if (s_last) {
        int t = threadIdx.x;
        if (t == 0) {
            float ls = atomicAdd(&g_loss[0], 0.0f);
            float lc = atomicAdd(&g_loss[1], 0.0f);
            out[0] = ls / (lc + EPSF);     // LOSS_WEIGHT = 1
            g_loss[0] = 0.0f;
            g_loss[1] = 0.0f;
            g_done = 0u;
        }
        float4 z4 = make_float4(0.0f, 0.0f, 0.0f, 0.0f);
        for (int i = t; i < BS * NV; i += 256) g_vn[i] = z4;
        for (int i = t; i < BS * NSUB; i += 256) g_cnt3[i] = 0;
    }
}

// ---------------------------------------------------------------------------
extern "C" void kernel_launch(void* const* d_in, const int* in_sizes, int n_in,
                              void* d_out, int out_size) {
    const float* pred    = (const float*)d_in[0];   // (2, 8192, 3)
    const float* h_state = (const float*)d_in[2];   // (2, 6, 6890)
    const int*   h_faces = (const int*)d_in[3];     // (2, 3, 13776)
    float* out = (float*)d_out;

    int bn = BS * NF;   // covers BS*NV too (NF > NV)
    build_kernel<<<(bn + 127) / 128, 128>>>(h_state, h_faces);

    query_kernel<<<QBLOCKS, 256>>>(pred, h_state, out);
}